// round 4
// baseline (speedup 1.0000x reference)
#include <cuda_runtime.h>
#include <cuda_bf16.h>
#include <math.h>

#define B_DIM 32
#define H_DIM 56
#define W_DIM 56
#define C_DIM 256
#define NPIX (B_DIM * H_DIM * W_DIM)   // 100352
#define HW (H_DIM * W_DIM)             // 3136
#define HALF_B (B_DIM / 2)             // 16
#define HALF_PIX (HALF_B * HW)         // 50176

// Scratch (no cudaMalloc allowed): pooled [avg,max] and attn map per pixel.
__device__ float2 g_pooled[NPIX];
__device__ float  g_attn[NPIX];

// ---------------------------------------------------------------------------
// Kernel 1: channel mean+max pool over a batch-half.
// 4 pixels per warp, 8 lanes per pixel, 8 front-batched float4 per lane.
// Each load instruction: 4 fully-used 128B lines, perfectly coalesced.
// Leaves this half of x resident in L2 (51.5MB << 126MB).
// ---------------------------------------------------------------------------
__global__ void __launch_bounds__(256) pool_kernel(const float* __restrict__ x,
                                                   int pix_off) {
    int warp = (blockIdx.x * blockDim.x + threadIdx.x) >> 5;
    int lane = threadIdx.x & 31;
    int sub  = lane >> 3;          // which of the warp's 4 pixels
    int co   = lane & 7;           // float4 slot within pixel
    int pix  = pix_off + warp * 4 + sub;

    const float4* __restrict__ xr = (const float4*)(x + (size_t)pix * C_DIM);
    float4 v0 = xr[co];
    float4 v1 = xr[co + 8];
    float4 v2 = xr[co + 16];
    float4 v3 = xr[co + 24];
    float4 v4 = xr[co + 32];
    float4 v5 = xr[co + 40];
    float4 v6 = xr[co + 48];
    float4 v7 = xr[co + 56];

    float s = (((v0.x + v0.y) + (v0.z + v0.w)) + ((v1.x + v1.y) + (v1.z + v1.w)))
            + (((v2.x + v2.y) + (v2.z + v2.w)) + ((v3.x + v3.y) + (v3.z + v3.w)))
            + (((v4.x + v4.y) + (v4.z + v4.w)) + ((v5.x + v5.y) + (v5.z + v5.w)))
            + (((v6.x + v6.y) + (v6.z + v6.w)) + ((v7.x + v7.y) + (v7.z + v7.w)));

    float m01 = fmaxf(fmaxf(fmaxf(v0.x, v0.y), fmaxf(v0.z, v0.w)),
                      fmaxf(fmaxf(v1.x, v1.y), fmaxf(v1.z, v1.w)));
    float m23 = fmaxf(fmaxf(fmaxf(v2.x, v2.y), fmaxf(v2.z, v2.w)),
                      fmaxf(fmaxf(v3.x, v3.y), fmaxf(v3.z, v3.w)));
    float m45 = fmaxf(fmaxf(fmaxf(v4.x, v4.y), fmaxf(v4.z, v4.w)),
                      fmaxf(fmaxf(v5.x, v5.y), fmaxf(v5.z, v5.w)));
    float m67 = fmaxf(fmaxf(fmaxf(v6.x, v6.y), fmaxf(v6.z, v6.w)),
                      fmaxf(fmaxf(v7.x, v7.y), fmaxf(v7.z, v7.w)));
    float m = fmaxf(fmaxf(m01, m23), fmaxf(m45, m67));

    #pragma unroll
    for (int off = 4; off; off >>= 1) {
        s += __shfl_xor_sync(0xffffffffu, s, off);
        m = fmaxf(m, __shfl_xor_sync(0xffffffffu, m, off));
    }

    if (co == 0) {
        g_pooled[pix] = make_float2(s * (1.0f / 256.0f), m);
    }
}

// ---------------------------------------------------------------------------
// Kernel 2: 7x7 SAME conv over pooled map -> sigmoid -> attn map (batch-half).
// 16x16 pixel tile per block, 22x22 float2 halo in smem, weights in smem.
// Pooled map is tiny and L2-hot.
// ---------------------------------------------------------------------------
__global__ void __launch_bounds__(256) conv_attn_kernel(
    const float* __restrict__ w,     // [7,7,2,1] HWIO
    const float* __restrict__ bias,  // [1]
    int batch_off)
{
    __shared__ float2 tile[22][22];
    __shared__ float  ws[98];
    __shared__ float  bs;

    int bb  = batch_off + blockIdx.z;
    int ty0 = blockIdx.y * 16;
    int tx0 = blockIdx.x * 16;
    int tid = threadIdx.y * 16 + threadIdx.x;

    if (tid < 98) ws[tid] = w[tid];
    if (tid == 127) bs = bias[0];

    const float2* __restrict__ pooled_b = g_pooled + bb * HW;
    #pragma unroll
    for (int i = tid; i < 22 * 22; i += 256) {
        int r = i / 22;
        int c = i - r * 22;
        int yy = ty0 + r - 3;
        int xx = tx0 + c - 3;
        float2 v = make_float2(0.0f, 0.0f);
        if (yy >= 0 && yy < H_DIM && xx >= 0 && xx < W_DIM)
            v = pooled_b[yy * W_DIM + xx];
        tile[r][c] = v;
    }
    __syncthreads();

    int hy = ty0 + threadIdx.y;
    int wx = tx0 + threadIdx.x;
    if (hy < H_DIM && wx < W_DIM) {
        float acc = bs;
        #pragma unroll
        for (int dy = 0; dy < 7; dy++) {
            #pragma unroll
            for (int dx = 0; dx < 7; dx++) {
                float2 p = tile[threadIdx.y + dy][threadIdx.x + dx];
                acc = fmaf(p.x, ws[(dy * 7 + dx) * 2 + 0], acc);
                acc = fmaf(p.y, ws[(dy * 7 + dx) * 2 + 1], acc);
            }
        }
        g_attn[bb * HW + hy * W_DIM + wx] = 1.0f / (1.0f + __expf(-acc));
    }
}

// ---------------------------------------------------------------------------
// Kernel 3: streaming scale over a batch-half: out = x * attn[pixel].
// x for this half is L2-resident from the pool pass; reads should mostly hit.
// __ldcs on x (last use), __stcs on out (never re-read -> preferred victim)
// protect the residency of the not-yet-read part of the half.
// 8 float4 per thread, block-strided, fully coalesced.
// ---------------------------------------------------------------------------
__global__ void __launch_bounds__(256) scale_kernel(
    const float* __restrict__ x,
    float* __restrict__ out,
    int f4_off)                       // float4 offset of this half
{
    int base = f4_off + blockIdx.x * 2048 + threadIdx.x;   // float4 index
    const float4* __restrict__ xr = (const float4*)x;
    float4* __restrict__ o = (float4*)out;

    float4 v[8];
    float  a[8];
    #pragma unroll
    for (int j = 0; j < 8; j++)
        v[j] = __ldcs(&xr[base + j * 256]);
    #pragma unroll
    for (int j = 0; j < 8; j++)
        a[j] = __ldg(&g_attn[(base + j * 256) >> 6]);

    #pragma unroll
    for (int j = 0; j < 8; j++) {
        v[j].x *= a[j]; v[j].y *= a[j]; v[j].z *= a[j]; v[j].w *= a[j];
    }

    #pragma unroll
    for (int j = 0; j < 8; j++)
        __stcs(&o[base + j * 256], v[j]);
}

extern "C" void kernel_launch(void* const* d_in, const int* in_sizes, int n_in,
                              void* d_out, int out_size) {
    const float* x  = (const float*)d_in[0];
    const float* w  = (const float*)d_in[1];
    const float* b  = (const float*)d_in[2];
    float* out = (float*)d_out;

    // Per half: 50176 pixels.
    const int pool_blocks  = (HALF_PIX / 4) / 8;                // 1568
    const int scale_blocks = (HALF_PIX * (C_DIM / 4)) / 2048;   // 1568
    dim3 cgrid((W_DIM + 15) / 16, (H_DIM + 15) / 16, HALF_B);   // 4x4x16

    // Half 1 (batches 0..15)
    pool_kernel<<<pool_blocks, 256>>>(x, 0);
    conv_attn_kernel<<<cgrid, dim3(16, 16)>>>(w, b, 0);
    scale_kernel<<<scale_blocks, 256>>>(x, out, 0);

    // Half 2 (batches 16..31)
    pool_kernel<<<pool_blocks, 256>>>(x, HALF_PIX);
    conv_attn_kernel<<<cgrid, dim3(16, 16)>>>(w, b, HALF_B);
    scale_kernel<<<scale_blocks, 256>>>(x, out, HALF_PIX * (C_DIM / 4));
}

// round 6
// speedup vs baseline: 1.0754x; 1.0754x over previous
#include <cuda_runtime.h>
#include <cuda_bf16.h>
#include <math.h>

#define B_DIM 32
#define H_DIM 56
#define W_DIM 56
#define C_DIM 256
#define NPIX (B_DIM * H_DIM * W_DIM)   // 100352
#define HW (H_DIM * W_DIM)             // 3136

// Scratch (no cudaMalloc allowed): pooled [avg,max] and attn map per pixel.
__device__ float2 g_pooled[NPIX];
__device__ float  g_attn[NPIX];

// 32-byte load (8 floats) with L2 evict_last priority. sm_103 ptxas only
// allows the evict_last modifier on .v8.b32 / .v4.b64 (32B) loads.
struct f8 { float4 a, b; };
__device__ __forceinline__ f8 ldg_f8_evict_last(const float* p) {
    f8 r;
    unsigned long long d0, d1, d2, d3;
    asm volatile("ld.global.L2::evict_last.v4.b64 {%0,%1,%2,%3}, [%4];"
                 : "=l"(d0), "=l"(d1), "=l"(d2), "=l"(d3)
                 : "l"(p));
    r.a.x = __uint_as_float((unsigned)(d0));
    r.a.y = __uint_as_float((unsigned)(d0 >> 32));
    r.a.z = __uint_as_float((unsigned)(d1));
    r.a.w = __uint_as_float((unsigned)(d1 >> 32));
    r.b.x = __uint_as_float((unsigned)(d2));
    r.b.y = __uint_as_float((unsigned)(d2 >> 32));
    r.b.z = __uint_as_float((unsigned)(d3));
    r.b.w = __uint_as_float((unsigned)(d3 >> 32));
    return r;
}

// ---------------------------------------------------------------------------
// Kernel 1: channel mean+max pool. 4 pixels per warp, 8 lanes per pixel.
// 4 front-batched 32B loads per lane (covers 256 channels), all evict_last.
// Per instruction the warp reads 8 fully-used 128B lines, coalesced.
// ---------------------------------------------------------------------------
__global__ void __launch_bounds__(256) pool_kernel(const float* __restrict__ x) {
    int warp = (blockIdx.x * blockDim.x + threadIdx.x) >> 5;
    int lane = threadIdx.x & 31;
    int sub  = lane >> 3;          // which of the warp's 4 pixels
    int co   = lane & 7;           // 32B slot within pixel
    int pix  = warp * 4 + sub;
    if (pix >= NPIX) return;

    const float* __restrict__ xr = x + (size_t)pix * C_DIM;
    f8 u0 = ldg_f8_evict_last(xr + co * 8);
    f8 u1 = ldg_f8_evict_last(xr + co * 8 + 64);
    f8 u2 = ldg_f8_evict_last(xr + co * 8 + 128);
    f8 u3 = ldg_f8_evict_last(xr + co * 8 + 192);

    float4 v0 = u0.a, v1 = u0.b, v2 = u1.a, v3 = u1.b;
    float4 v4 = u2.a, v5 = u2.b, v6 = u3.a, v7 = u3.b;

    float s = (((v0.x + v0.y) + (v0.z + v0.w)) + ((v1.x + v1.y) + (v1.z + v1.w)))
            + (((v2.x + v2.y) + (v2.z + v2.w)) + ((v3.x + v3.y) + (v3.z + v3.w)))
            + (((v4.x + v4.y) + (v4.z + v4.w)) + ((v5.x + v5.y) + (v5.z + v5.w)))
            + (((v6.x + v6.y) + (v6.z + v6.w)) + ((v7.x + v7.y) + (v7.z + v7.w)));

    float m01 = fmaxf(fmaxf(fmaxf(v0.x, v0.y), fmaxf(v0.z, v0.w)),
                      fmaxf(fmaxf(v1.x, v1.y), fmaxf(v1.z, v1.w)));
    float m23 = fmaxf(fmaxf(fmaxf(v2.x, v2.y), fmaxf(v2.z, v2.w)),
                      fmaxf(fmaxf(v3.x, v3.y), fmaxf(v3.z, v3.w)));
    float m45 = fmaxf(fmaxf(fmaxf(v4.x, v4.y), fmaxf(v4.z, v4.w)),
                      fmaxf(fmaxf(v5.x, v5.y), fmaxf(v5.z, v5.w)));
    float m67 = fmaxf(fmaxf(fmaxf(v6.x, v6.y), fmaxf(v6.z, v6.w)),
                      fmaxf(fmaxf(v7.x, v7.y), fmaxf(v7.z, v7.w)));
    float m = fmaxf(fmaxf(m01, m23), fmaxf(m45, m67));

    #pragma unroll
    for (int off = 4; off; off >>= 1) {
        s += __shfl_xor_sync(0xffffffffu, s, off);
        m = fmaxf(m, __shfl_xor_sync(0xffffffffu, m, off));
    }

    if (co == 0) {
        g_pooled[pix] = make_float2(s * (1.0f / 256.0f), m);
    }
}

// ---------------------------------------------------------------------------
// Kernel 2: 7x7 SAME conv over pooled map -> sigmoid -> attn map.
// 16x16 pixel tile per block, 22x22 float2 halo in smem, weights in smem.
// Only 512 blocks; pooled map (0.8MB) is L2-hot.
// ---------------------------------------------------------------------------
__global__ void __launch_bounds__(256) conv_attn_kernel(
    const float* __restrict__ w,     // [7,7,2,1] HWIO
    const float* __restrict__ bias)  // [1]
{
    __shared__ float2 tile[22][22];
    __shared__ float  ws[98];
    __shared__ float  bs;

    int bb  = blockIdx.z;
    int ty0 = blockIdx.y * 16;
    int tx0 = blockIdx.x * 16;
    int tid = threadIdx.y * 16 + threadIdx.x;

    if (tid < 98) ws[tid] = w[tid];
    if (tid == 127) bs = bias[0];

    const float2* __restrict__ pooled_b = g_pooled + bb * HW;
    #pragma unroll
    for (int i = tid; i < 22 * 22; i += 256) {
        int r = i / 22;
        int c = i - r * 22;
        int yy = ty0 + r - 3;
        int xx = tx0 + c - 3;
        float2 v = make_float2(0.0f, 0.0f);
        if (yy >= 0 && yy < H_DIM && xx >= 0 && xx < W_DIM)
            v = pooled_b[yy * W_DIM + xx];
        tile[r][c] = v;
    }
    __syncthreads();

    int hy = ty0 + threadIdx.y;
    int wx = tx0 + threadIdx.x;
    if (hy < H_DIM && wx < W_DIM) {
        float acc = bs;
        #pragma unroll
        for (int dy = 0; dy < 7; dy++) {
            #pragma unroll
            for (int dx = 0; dx < 7; dx++) {
                float2 p = tile[threadIdx.y + dy][threadIdx.x + dx];
                acc = fmaf(p.x, ws[(dy * 7 + dx) * 2 + 0], acc);
                acc = fmaf(p.y, ws[(dy * 7 + dx) * 2 + 1], acc);
            }
        }
        g_attn[bb * HW + hy * W_DIM + wx] = 1.0f / (1.0f + __expf(-acc));
    }
}

// ---------------------------------------------------------------------------
// Kernel 3: streaming scale: out = x * attn[pixel].
// x is L2-resident in the evict_last class from the pool pass.
// __ldcs on x: hit demotes to evict-first (last use). __stcs on out:
// evict-first allocation -> out lines are the victims, not x.
// Reverse block order consumes the MRU tail first.
// 8 float4 per thread, block-strided, fully coalesced.
// ---------------------------------------------------------------------------
__global__ void __launch_bounds__(256) scale_kernel(
    const float* __restrict__ x,
    float* __restrict__ out)
{
    int blk = gridDim.x - 1 - blockIdx.x;
    int base = blk * 2048 + threadIdx.x;   // float4 index
    const float4* __restrict__ xr = (const float4*)x;
    float4* __restrict__ o = (float4*)out;

    float4 v[8];
    float  a[8];
    #pragma unroll
    for (int j = 0; j < 8; j++)
        v[j] = __ldcs(&xr[base + j * 256]);
    #pragma unroll
    for (int j = 0; j < 8; j++)
        a[j] = __ldg(&g_attn[(base + j * 256) >> 6]);

    #pragma unroll
    for (int j = 0; j < 8; j++) {
        v[j].x *= a[j]; v[j].y *= a[j]; v[j].z *= a[j]; v[j].w *= a[j];
    }

    #pragma unroll
    for (int j = 0; j < 8; j++)
        __stcs(&o[base + j * 256], v[j]);
}

extern "C" void kernel_launch(void* const* d_in, const int* in_sizes, int n_in,
                              void* d_out, int out_size) {
    const float* x  = (const float*)d_in[0];
    const float* w  = (const float*)d_in[1];
    const float* b  = (const float*)d_in[2];
    float* out = (float*)d_out;

    const int pool_blocks = (NPIX / 4) / 8;       // 3136
    pool_kernel<<<pool_blocks, 256>>>(x);

    dim3 cgrid((W_DIM + 15) / 16, (H_DIM + 15) / 16, B_DIM);  // 4x4x32
    conv_attn_kernel<<<cgrid, dim3(16, 16)>>>(w, b);

    const int scale_blocks = (NPIX * (C_DIM / 4)) / 2048;     // 3136
    scale_kernel<<<scale_blocks, 256>>>(x, out);
}